// round 1
// baseline (speedup 1.0000x reference)
#include <cuda_runtime.h>
#include <math.h>

#define RANGE_MIN (-5.0f)
#define RANGE_MAX (5.0f)
#define MIN_BIN_SIZE 0.0001f
#define MIN_SLOPE 0.0001f
#define KBINS 8

// Packed table in device global memory, filled by prep kernel:
// [b*8 + 0..7] for b in 0..7: x_k, inv_w, y_k, h, s, c(=dk+dk1-2s), d_k, d_k1
// [64..70]: interior knots x_pos[1..7]
// [71]: slope_left  [72]: slope_right  [73]: log(slope_left)  [74]: log(slope_right)
__device__ __align__(16) float g_tab[80];

__global__ void rqs_prep_kernel(const float* __restrict__ p) {
    if (threadIdx.x != 0 || blockIdx.x != 0) return;

    float w[KBINS], h[KBINS], d[KBINS + 1];
    // softmax(widths), softmax(heights) with max-subtraction (match jax.nn.softmax)
    float mw = -1e30f, mh = -1e30f;
    for (int i = 0; i < KBINS; i++) {
        mw = fmaxf(mw, p[i]);
        mh = fmaxf(mh, p[KBINS + i]);
    }
    float sw = 0.f, sh = 0.f;
    for (int i = 0; i < KBINS; i++) {
        w[i] = expf(p[i] - mw);         sw += w[i];
        h[i] = expf(p[KBINS + i] - mh); sh += h[i];
    }
    const float total = RANGE_MAX - RANGE_MIN;
    const float scale = total - KBINS * MIN_BIN_SIZE;
    for (int i = 0; i < KBINS; i++) {
        w[i] = w[i] / sw * scale + MIN_BIN_SIZE;
        h[i] = h[i] / sh * scale + MIN_BIN_SIZE;
    }
    // slopes: softplus(p + offset) + MIN_SLOPE
    const float off = logf(expf(1.0f - MIN_SLOPE) - 1.0f);
    for (int i = 0; i <= KBINS; i++) {
        float z = p[2 * KBINS + i] + off;
        d[i] = ((z > 20.f) ? z : log1pf(expf(z))) + MIN_SLOPE;
    }
    // cumsum positions
    float xp[KBINS + 1], yp[KBINS + 1];
    xp[0] = RANGE_MIN; yp[0] = RANGE_MIN;
    float cx = 0.f, cy = 0.f;
    for (int i = 0; i < KBINS; i++) {
        cx += w[i]; xp[i + 1] = RANGE_MIN + cx;
        cy += h[i]; yp[i + 1] = RANGE_MIN + cy;
    }
    // per-bin packed struct (recompute width/height from positions to match reference)
    for (int b = 0; b < KBINS; b++) {
        float xk  = xp[b];
        float wid = xp[b + 1] - xp[b];
        float yk  = yp[b];
        float hei = yp[b + 1] - yp[b];
        float inv_w = 1.0f / wid;
        float s = hei / wid;
        float c = d[b + 1] + d[b] - 2.0f * s;
        g_tab[b * 8 + 0] = xk;
        g_tab[b * 8 + 1] = inv_w;
        g_tab[b * 8 + 2] = yk;
        g_tab[b * 8 + 3] = hei;
        g_tab[b * 8 + 4] = s;
        g_tab[b * 8 + 5] = c;
        g_tab[b * 8 + 6] = d[b];
        g_tab[b * 8 + 7] = d[b + 1];
    }
    for (int i = 0; i < 7; i++) g_tab[64 + i] = xp[1 + i];
    g_tab[71] = d[0];
    g_tab[72] = d[KBINS];
    g_tab[73] = logf(d[0]);
    g_tab[74] = logf(d[KBINS]);
    for (int i = 75; i < 80; i++) g_tab[i] = 0.f;
}

__device__ __forceinline__ void rqs_eval(float xx, const float* stab,
                                         float k1, float k2, float k3, float k4,
                                         float k5, float k6, float k7,
                                         float sl, float sr, float lsl, float lsr,
                                         float& y_out, float& ld_out) {
    // searchsorted(x_pos[1:-1], x, side='right'): count knots <= x
    int b = (xx >= k1) + (xx >= k2) + (xx >= k3) + (xx >= k4) +
            (xx >= k5) + (xx >= k6) + (xx >= k7);
    const float4 lo = *reinterpret_cast<const float4*>(&stab[b * 8]);     // x_k, inv_w, y_k, h
    const float4 hi = *reinterpret_cast<const float4*>(&stab[b * 8 + 4]); // s, c, d_k, d_k1

    float xi = (xx - lo.x) * lo.y;
    xi = fminf(fmaxf(xi, 0.0f), 1.0f);
    float omxi = 1.0f - xi;
    float xom  = xi * omxi;

    float s  = hi.x, c = hi.y, dk = hi.z, dk1 = hi.w;
    float num = fmaf(s * xi, xi, dk * xom);          // s*xi^2 + dk*xi*(1-xi)
    float den = fmaf(c, xom, s);                     // s + (dk1+dk-2s)*xi*(1-xi)
    float r   = __fdividef(1.0f, den);
    float y   = fmaf(lo.w * num, r, lo.z);           // y_k + h*num/den

    // derivative numerator: s^2 * (dk1*xi^2 + 2s*xi(1-xi) + dk*(1-xi)^2)
    float inner = fmaf(dk1 * xi, xi, fmaf(2.0f * s, xom, dk * omxi * omxi));
    float deriv = (s * s) * inner * r * r;
    float ld = __logf(deriv);

    // out-of-range linear tails
    bool below = xx < RANGE_MIN;
    bool above = xx > RANGE_MAX;
    float y_left  = fmaf(xx - RANGE_MIN, sl, RANGE_MIN);
    float y_right = fmaf(xx - RANGE_MAX, sr, RANGE_MAX);
    y  = below ? y_left  : (above ? y_right : y);
    ld = below ? lsl     : (above ? lsr     : ld);

    y_out = y;
    ld_out = ld;
}

__global__ void __launch_bounds__(256) rqs_main_kernel(
    const float4* __restrict__ x4,
    float4* __restrict__ y4,
    float4* __restrict__ ld4,
    int n4,
    const float* __restrict__ x_scalar,
    float* __restrict__ y_scalar,
    float* __restrict__ ld_scalar,
    int n_total
) {
    __shared__ __align__(16) float stab[80];
    if (threadIdx.x < 80) stab[threadIdx.x] = g_tab[threadIdx.x];
    __syncthreads();

    const float k1 = stab[64], k2 = stab[65], k3 = stab[66], k4 = stab[67];
    const float k5 = stab[68], k6 = stab[69], k7 = stab[70];
    const float sl = stab[71], sr = stab[72], lsl = stab[73], lsr = stab[74];

    const int stride = gridDim.x * blockDim.x;
    for (int i = blockIdx.x * blockDim.x + threadIdx.x; i < n4; i += stride) {
        float4 xv = x4[i];
        float4 yv, lv;
        rqs_eval(xv.x, stab, k1,k2,k3,k4,k5,k6,k7, sl,sr,lsl,lsr, yv.x, lv.x);
        rqs_eval(xv.y, stab, k1,k2,k3,k4,k5,k6,k7, sl,sr,lsl,lsr, yv.y, lv.y);
        rqs_eval(xv.z, stab, k1,k2,k3,k4,k5,k6,k7, sl,sr,lsl,lsr, yv.z, lv.z);
        rqs_eval(xv.w, stab, k1,k2,k3,k4,k5,k6,k7, sl,sr,lsl,lsr, yv.w, lv.w);
        y4[i]  = yv;
        ld4[i] = lv;
    }

    // scalar tail (n_total not multiple of 4)
    int tail_start = n4 * 4;
    int rem = n_total - tail_start;
    int gtid = blockIdx.x * blockDim.x + threadIdx.x;
    if (gtid < rem) {
        int idx = tail_start + gtid;
        float yy, ll;
        rqs_eval(x_scalar[idx], stab, k1,k2,k3,k4,k5,k6,k7, sl,sr,lsl,lsr, yy, ll);
        y_scalar[idx]  = yy;
        ld_scalar[idx] = ll;
    }
}

extern "C" void kernel_launch(void* const* d_in, const int* in_sizes, int n_in,
                              void* d_out, int out_size) {
    const float* x = (const float*)d_in[0];
    const float* p = (const float*)d_in[1];
    float* out = (float*)d_out;
    const int n = in_sizes[0];

    float* y_ptr  = out;       // out[0:N]   = y
    float* ld_ptr = out + n;   // out[N:2N]  = logdet

    rqs_prep_kernel<<<1, 32>>>(p);

    const int n4 = n / 4;
    const int threads = 256;
    const int blocks = 148 * 8;  // grid-stride, ~full occupancy on 148-152 SMs
    rqs_main_kernel<<<blocks, threads>>>(
        (const float4*)x, (float4*)y_ptr, (float4*)ld_ptr, n4,
        x, y_ptr, ld_ptr, n);
}

// round 2
// speedup vs baseline: 1.0215x; 1.0215x over previous
#include <cuda_runtime.h>
#include <math.h>

#define RANGE_MIN (-5.0f)
#define RANGE_MAX (5.0f)
#define MIN_BIN_SIZE 0.0001f
#define MIN_SLOPE 0.0001f
#define KBINS 8

// Packed table, stride 12 floats (48B) per bin => conflict-free LDS.128:
//   bank group of bin b = (b*12)%32 = {0,12,24,4,16,28,8,20} — all disjoint.
// [b*12 + 0..7]: x_k, inv_w, y_k, h, s, c(=dk+dk1-2s), d_k, d_k1  (8..11 pad)
// [96..102]: interior knots x_pos[1..7]
// [103]=sl [104]=sr [105]=log(sl) [106]=log(sr)
__device__ __align__(16) float g_tab[112];

__global__ void rqs_prep_kernel(const float* __restrict__ p) {
    if (threadIdx.x != 0 || blockIdx.x != 0) return;

    float w[KBINS], h[KBINS], d[KBINS + 1];
    float mw = -1e30f, mh = -1e30f;
    for (int i = 0; i < KBINS; i++) {
        mw = fmaxf(mw, p[i]);
        mh = fmaxf(mh, p[KBINS + i]);
    }
    float sw = 0.f, sh = 0.f;
    for (int i = 0; i < KBINS; i++) {
        w[i] = expf(p[i] - mw);         sw += w[i];
        h[i] = expf(p[KBINS + i] - mh); sh += h[i];
    }
    const float total = RANGE_MAX - RANGE_MIN;
    const float scale = total - KBINS * MIN_BIN_SIZE;
    for (int i = 0; i < KBINS; i++) {
        w[i] = w[i] / sw * scale + MIN_BIN_SIZE;
        h[i] = h[i] / sh * scale + MIN_BIN_SIZE;
    }
    const float off = logf(expf(1.0f - MIN_SLOPE) - 1.0f);
    for (int i = 0; i <= KBINS; i++) {
        float z = p[2 * KBINS + i] + off;
        d[i] = ((z > 20.f) ? z : log1pf(expf(z))) + MIN_SLOPE;
    }
    float xp[KBINS + 1], yp[KBINS + 1];
    xp[0] = RANGE_MIN; yp[0] = RANGE_MIN;
    float cx = 0.f, cy = 0.f;
    for (int i = 0; i < KBINS; i++) {
        cx += w[i]; xp[i + 1] = RANGE_MIN + cx;
        cy += h[i]; yp[i + 1] = RANGE_MIN + cy;
    }
    for (int i = 0; i < 112; i++) g_tab[i] = 0.f;
    for (int b = 0; b < KBINS; b++) {
        float xk  = xp[b];
        float wid = xp[b + 1] - xp[b];
        float yk  = yp[b];
        float hei = yp[b + 1] - yp[b];
        g_tab[b * 12 + 0] = xk;
        g_tab[b * 12 + 1] = 1.0f / wid;
        g_tab[b * 12 + 2] = yk;
        g_tab[b * 12 + 3] = hei;
        float s = hei / wid;
        g_tab[b * 12 + 4] = s;
        g_tab[b * 12 + 5] = d[b + 1] + d[b] - 2.0f * s;
        g_tab[b * 12 + 6] = d[b];
        g_tab[b * 12 + 7] = d[b + 1];
    }
    for (int i = 0; i < 7; i++) g_tab[96 + i] = xp[1 + i];
    g_tab[103] = d[0];
    g_tab[104] = d[KBINS];
    g_tab[105] = logf(d[0]);
    g_tab[106] = logf(d[KBINS]);
}

__device__ __forceinline__ void rqs_eval(float xx, const float* __restrict__ stab,
                                         float k1, float k2, float k3, float k4,
                                         float k5, float k6, float k7,
                                         float sl, float sr, float lsl, float lsr,
                                         float& y_out, float& ld_out) {
    int b = (xx >= k1) + (xx >= k2) + (xx >= k3) + (xx >= k4) +
            (xx >= k5) + (xx >= k6) + (xx >= k7);
    const float4 lo = *reinterpret_cast<const float4*>(&stab[b * 12]);     // x_k, inv_w, y_k, h
    const float4 hi = *reinterpret_cast<const float4*>(&stab[b * 12 + 4]); // s, c, d_k, d_k1

    float xi = (xx - lo.x) * lo.y;
    xi = fminf(fmaxf(xi, 0.0f), 1.0f);
    float omxi = 1.0f - xi;
    float xom  = xi * omxi;

    float s  = hi.x, c = hi.y, dk = hi.z, dk1 = hi.w;
    float num = fmaf(s * xi, xi, dk * xom);          // s*xi^2 + dk*xi*(1-xi)
    float den = fmaf(c, xom, s);                     // s + (dk1+dk-2s)*xi*(1-xi)
    float r   = __fdividef(1.0f, den);
    float y   = fmaf(lo.w * num, r, lo.z);           // y_k + h*num/den

    float inner = fmaf(dk1 * xi, xi, fmaf(2.0f * s, xom, dk * omxi * omxi));
    float srr = s * r;
    float deriv = srr * srr * inner;                 // s^2 * inner / den^2
    float ld = __logf(deriv);

    bool below = xx < RANGE_MIN;
    bool above = xx > RANGE_MAX;
    float y_left  = fmaf(xx - RANGE_MIN, sl, RANGE_MIN);
    float y_right = fmaf(xx - RANGE_MAX, sr, RANGE_MAX);
    y  = below ? y_left  : (above ? y_right : y);
    ld = below ? lsl     : (above ? lsr     : ld);

    y_out = y;
    ld_out = ld;
}

// Flat launch: each thread handles 2 float4s (8 elements). No grid-stride loop.
__global__ void __launch_bounds__(256, 6) rqs_main_kernel(
    const float4* __restrict__ x4,
    float4* __restrict__ y4,
    float4* __restrict__ ld4,
    int n4
) {
    __shared__ __align__(16) float stab[112];
    if (threadIdx.x < 112) stab[threadIdx.x] = g_tab[threadIdx.x];
    __syncthreads();

    const float k1 = stab[96],  k2 = stab[97],  k3 = stab[98],  k4 = stab[99];
    const float k5 = stab[100], k6 = stab[101], k7 = stab[102];
    const float sl = stab[103], sr = stab[104], lsl = stab[105], lsr = stab[106];

    int i0 = blockIdx.x * 512 + threadIdx.x;
#pragma unroll
    for (int u = 0; u < 2; u++) {
        int i = i0 + u * 256;
        if (i < n4) {
            float4 xv = __ldcs(&x4[i]);
            float4 yv, lv;
            rqs_eval(xv.x, stab, k1,k2,k3,k4,k5,k6,k7, sl,sr,lsl,lsr, yv.x, lv.x);
            rqs_eval(xv.y, stab, k1,k2,k3,k4,k5,k6,k7, sl,sr,lsl,lsr, yv.y, lv.y);
            rqs_eval(xv.z, stab, k1,k2,k3,k4,k5,k6,k7, sl,sr,lsl,lsr, yv.z, lv.z);
            rqs_eval(xv.w, stab, k1,k2,k3,k4,k5,k6,k7, sl,sr,lsl,lsr, yv.w, lv.w);
            __stcs(&y4[i],  yv);
            __stcs(&ld4[i], lv);
        }
    }
}

// Tail kernel (launched only if n % 4 != 0; for N=2^25 it never runs)
__global__ void rqs_tail_kernel(const float* __restrict__ x,
                                float* __restrict__ y,
                                float* __restrict__ ld,
                                int start, int n) {
    __shared__ __align__(16) float stab[112];
    if (threadIdx.x < 112) stab[threadIdx.x] = g_tab[threadIdx.x];
    __syncthreads();
    int idx = start + blockIdx.x * blockDim.x + threadIdx.x;
    if (idx < n) {
        float yy, ll;
        rqs_eval(x[idx], stab,
                 stab[96], stab[97], stab[98], stab[99], stab[100], stab[101], stab[102],
                 stab[103], stab[104], stab[105], stab[106], yy, ll);
        y[idx]  = yy;
        ld[idx] = ll;
    }
}

extern "C" void kernel_launch(void* const* d_in, const int* in_sizes, int n_in,
                              void* d_out, int out_size) {
    const float* x = (const float*)d_in[0];
    const float* p = (const float*)d_in[1];
    float* out = (float*)d_out;
    const int n = in_sizes[0];

    float* y_ptr  = out;       // out[0:N]  = y
    float* ld_ptr = out + n;   // out[N:2N] = logdet

    rqs_prep_kernel<<<1, 32>>>(p);

    const int n4 = n / 4;
    const int blocks = (n4 + 511) / 512;
    rqs_main_kernel<<<blocks, 256>>>(
        (const float4*)x, (float4*)y_ptr, (float4*)ld_ptr, n4);

    const int rem = n - n4 * 4;
    if (rem > 0) {
        rqs_tail_kernel<<<1, 256>>>(x, y_ptr, ld_ptr, n4 * 4, n);
    }
}

// round 3
// speedup vs baseline: 1.1889x; 1.1639x over previous
#include <cuda_runtime.h>
#include <math.h>

#define RANGE_MIN (-5.0f)
#define RANGE_MAX (5.0f)
#define MIN_BIN_SIZE 0.0001f
#define MIN_SLOPE 0.0001f
#define KBINS 8

// Packed table, stride 12 floats (48B) per bin => conflict-free LDS:
//   bank group of bin b = (b*12)%32 = {0,12,24,4,16,28,8,20} — all disjoint.
// [b*12 + 0..8]: nxkw(=-x_k*inv_w), inv_w, y_k, h, s, c(=dk+dk1-2s), d_k, d_k1, edge
//   edge = d0 for bin 0, d8 for bin 7, 0 otherwise (tail slope; (x-xc)==0 in-range)
// [96..102]: interior knots x_pos[1..7]
__device__ __align__(16) float g_tab[112];

__global__ void rqs_prep_kernel(const float* __restrict__ p) {
    if (threadIdx.x != 0 || blockIdx.x != 0) return;

    float w[KBINS], h[KBINS], d[KBINS + 1];
    float mw = -1e30f, mh = -1e30f;
    for (int i = 0; i < KBINS; i++) {
        mw = fmaxf(mw, p[i]);
        mh = fmaxf(mh, p[KBINS + i]);
    }
    float sw = 0.f, sh = 0.f;
    for (int i = 0; i < KBINS; i++) {
        w[i] = expf(p[i] - mw);         sw += w[i];
        h[i] = expf(p[KBINS + i] - mh); sh += h[i];
    }
    const float total = RANGE_MAX - RANGE_MIN;
    const float scale = total - KBINS * MIN_BIN_SIZE;
    for (int i = 0; i < KBINS; i++) {
        w[i] = w[i] / sw * scale + MIN_BIN_SIZE;
        h[i] = h[i] / sh * scale + MIN_BIN_SIZE;
    }
    const float off = logf(expf(1.0f - MIN_SLOPE) - 1.0f);
    for (int i = 0; i <= KBINS; i++) {
        float z = p[2 * KBINS + i] + off;
        d[i] = ((z > 20.f) ? z : log1pf(expf(z))) + MIN_SLOPE;
    }
    float xp[KBINS + 1], yp[KBINS + 1];
    xp[0] = RANGE_MIN; yp[0] = RANGE_MIN;
    float cx = 0.f, cy = 0.f;
    for (int i = 0; i < KBINS; i++) {
        cx += w[i]; xp[i + 1] = RANGE_MIN + cx;
        cy += h[i]; yp[i + 1] = RANGE_MIN + cy;
    }
    for (int i = 0; i < 112; i++) g_tab[i] = 0.f;
    for (int b = 0; b < KBINS; b++) {
        float xk    = xp[b];
        float wid   = xp[b + 1] - xp[b];
        float yk    = yp[b];
        float hei   = yp[b + 1] - yp[b];
        float inv_w = 1.0f / wid;
        float s     = hei / wid;
        g_tab[b * 12 + 0] = -xk * inv_w;
        g_tab[b * 12 + 1] = inv_w;
        g_tab[b * 12 + 2] = yk;
        g_tab[b * 12 + 3] = hei;
        g_tab[b * 12 + 4] = s;
        g_tab[b * 12 + 5] = d[b + 1] + d[b] - 2.0f * s;
        g_tab[b * 12 + 6] = d[b];
        g_tab[b * 12 + 7] = d[b + 1];
        g_tab[b * 12 + 8] = (b == 0) ? d[0] : ((b == KBINS - 1) ? d[KBINS] : 0.0f);
    }
    for (int i = 0; i < 7; i++) g_tab[96 + i] = xp[1 + i];
}

__device__ __forceinline__ void rqs_eval(float xx, const float* __restrict__ stab,
                                         float k1, float k2, float k3, float k4,
                                         float k5, float k6, float k7,
                                         float& y_out, float& ld_out) {
    // clamp to range; spline at clamped point + linear tail correction
    float xc = fminf(fmaxf(xx, RANGE_MIN), RANGE_MAX);

    // binary searchsorted over 7 interior knots (side='right')
    bool  c2  = xc >= k4;
    float km1 = c2 ? k6 : k2;
    bool  c1  = xc >= km1;
    float kmA = c2 ? k7 : k3;
    float kmB = c2 ? k5 : k1;
    float km0 = c1 ? kmA : kmB;
    bool  c0  = xc >= km0;
    int boff = (c2 ? 192 : 0) + (c1 ? 96 : 0) + (c0 ? 48 : 0);

    const float* bp = (const float*)((const char*)stab + boff);
    const float4 lo = *reinterpret_cast<const float4*>(bp);      // nxkw, inv_w, y_k, h
    const float4 hi = *reinterpret_cast<const float4*>(bp + 4);  // s, c, d_k, d_k1
    const float edge = bp[8];

    float xi   = fmaf(xc, lo.y, lo.x);     // (xc - x_k) * inv_w
    float omxi = 1.0f - xi;
    float xom  = xi * omxi;

    float s = hi.x, cc = hi.y, dk = hi.z, dk1 = hi.w;
    float num = fmaf(s * xi, xi, dk * xom);    // s*xi^2 + dk*xi*(1-xi)
    float den = fmaf(cc, xom, s);              // s + (dk+dk1-2s)*xi*(1-xi)
    float r   = __fdividef(1.0f, den);

    float y = fmaf(lo.w * num, r, lo.z);       // y_k + h*num/den
    y = fmaf(xx - xc, edge, y);                // linear tail (0 in-range)

    // deriv = s^2*(dk1*xi^2 + 2s*xi(1-xi) + dk*(1-xi)^2)/den^2
    float t2    = dk * omxi;
    float t4    = fmaf(s + s, xom, t2 * omxi);
    float inner = fmaf(dk1 * xi, xi, t4);
    float srr   = s * r;
    ld_out = __logf(srr * srr * inner);        // == log(edge slope) at clamped bounds
    y_out  = y;
}

__global__ void __launch_bounds__(256, 6) rqs_main_kernel(
    const float4* __restrict__ x4,
    float4* __restrict__ y4,
    float4* __restrict__ ld4,
    int n4
) {
    __shared__ __align__(16) float stab[112];
    if (threadIdx.x < 112) stab[threadIdx.x] = g_tab[threadIdx.x];
    __syncthreads();

    const float k1 = stab[96],  k2 = stab[97],  k3 = stab[98],  k4 = stab[99];
    const float k5 = stab[100], k6 = stab[101], k7 = stab[102];

    int i0 = blockIdx.x * 512 + threadIdx.x;
#pragma unroll
    for (int u = 0; u < 2; u++) {
        int i = i0 + u * 256;
        if (i < n4) {
            float4 xv = __ldcs(&x4[i]);
            float4 yv, lv;
            rqs_eval(xv.x, stab, k1,k2,k3,k4,k5,k6,k7, yv.x, lv.x);
            rqs_eval(xv.y, stab, k1,k2,k3,k4,k5,k6,k7, yv.y, lv.y);
            rqs_eval(xv.z, stab, k1,k2,k3,k4,k5,k6,k7, yv.z, lv.z);
            rqs_eval(xv.w, stab, k1,k2,k3,k4,k5,k6,k7, yv.w, lv.w);
            __stcs(&y4[i],  yv);
            __stcs(&ld4[i], lv);
        }
    }
}

// Tail kernel (only if n % 4 != 0; for N=2^25 it never runs)
__global__ void rqs_tail_kernel(const float* __restrict__ x,
                                float* __restrict__ y,
                                float* __restrict__ ld,
                                int start, int n) {
    __shared__ __align__(16) float stab[112];
    if (threadIdx.x < 112) stab[threadIdx.x] = g_tab[threadIdx.x];
    __syncthreads();
    int idx = start + blockIdx.x * blockDim.x + threadIdx.x;
    if (idx < n) {
        float yy, ll;
        rqs_eval(x[idx], stab,
                 stab[96], stab[97], stab[98], stab[99],
                 stab[100], stab[101], stab[102], yy, ll);
        y[idx]  = yy;
        ld[idx] = ll;
    }
}

extern "C" void kernel_launch(void* const* d_in, const int* in_sizes, int n_in,
                              void* d_out, int out_size) {
    const float* x = (const float*)d_in[0];
    const float* p = (const float*)d_in[1];
    float* out = (float*)d_out;
    const int n = in_sizes[0];

    float* y_ptr  = out;       // out[0:N]  = y
    float* ld_ptr = out + n;   // out[N:2N] = logdet

    rqs_prep_kernel<<<1, 32>>>(p);

    const int n4 = n / 4;
    const int blocks = (n4 + 511) / 512;
    rqs_main_kernel<<<blocks, 256>>>(
        (const float4*)x, (float4*)y_ptr, (float4*)ld_ptr, n4);

    const int rem = n - n4 * 4;
    if (rem > 0) {
        rqs_tail_kernel<<<1, 256>>>(x, y_ptr, ld_ptr, n4 * 4, n);
    }
}